// round 10
// baseline (speedup 1.0000x reference)
#include <cuda_runtime.h>
#include <cstdint>

// PairwiseDistance: out[b,i,j] = ||x_i||^2 + ||y_j||^2 - 2*<x_i,y_j>
// Cross term via mma.sync tf32 (tcgen05 unavailable at harness .target sm_103).
// fp32 operands fed RAW to HMMA.tf32 (HW truncates to tf32 -> no cvt needed).
// Tiles staged via cp.async; exact-fp32 row norms computed from gmem (L2-hot)
// while the cp.async batch is in flight.  B=2, n=2048, d=64.

#define BATCH 2
#define NROWS 2048
#define DDIM  64

#define BM 128
#define BN 128
#define SK 68        // smem row stride in floats (64 + 4 pad) -> conflict-free

#define SMEM_X  0
#define SMEM_Y  (BM * SK * 4)
#define SMEM_XN (2 * BM * SK * 4)          // 128 floats
#define SMEM_YN (SMEM_XN + 512)
#define SMEM_TOTAL (SMEM_YN + 512)         // 70656 B

__device__ __forceinline__ uint32_t smem_u32(const void* p) {
    uint32_t a;
    asm("{ .reg .u64 t; cvta.to.shared.u64 t, %1; cvt.u32.u64 %0, t; }"
        : "=r"(a) : "l"(p));
    return a;
}

__global__ void __launch_bounds__(256, 2)
pdist_kernel(const float* __restrict__ x,
             const float* __restrict__ y,
             float* __restrict__ out) {
    extern __shared__ char smem[];
    uint32_t* xs = (uint32_t*)(smem + SMEM_X);
    uint32_t* ys = (uint32_t*)(smem + SMEM_Y);
    float* xn_s  = (float*)(smem + SMEM_XN);
    float* yn_s  = (float*)(smem + SMEM_YN);

    const int b  = blockIdx.z;
    const int i0 = blockIdx.y * BM;
    const int j0 = blockIdx.x * BN;
    const int tid = threadIdx.x;

    const float* xb = x + (size_t)b * NROWS * DDIM;
    const float* yb = y + (size_t)b * NROWS * DDIM;

    const int warp = tid >> 5;
    const int lane = tid & 31;
    const int wr = warp >> 2;          // 0..1
    const int wc = warp & 3;           // 0..3
    const int g   = lane >> 2;         // 0..7
    const int tig = lane & 3;          // 0..3

    // ---- stage tiles via cp.async: raw fp32, no cvt, no reg roundtrip ----
    // thread -> (row r, float4 chunk c); lanes cover consecutive k: coalesced.
    {
        const uint32_t xs_a = smem_u32(xs);
        const uint32_t ys_a = smem_u32(ys);
#pragma unroll
        for (int i = 0; i < 8; i++) {
            int e = tid + i * 256;         // 0..2047 float4 chunks
            int r = e >> 4;
            int c = e & 15;
            uint32_t dx = xs_a + (r * SK + c * 4) * 4;
            uint32_t dy = ys_a + (r * SK + c * 4) * 4;
            const float* sx = xb + (size_t)(i0 + r) * DDIM + c * 4;
            const float* sy = yb + (size_t)(j0 + r) * DDIM + c * 4;
            asm volatile("cp.async.cg.shared.global [%0], [%1], 16;"
                         :: "r"(dx), "l"(sx));
            asm volatile("cp.async.cg.shared.global [%0], [%1], 16;"
                         :: "r"(dy), "l"(sy));
        }
        asm volatile("cp.async.commit_group;");
    }

    // ---- exact fp32 row norms from gmem (L2-hot), overlapped with cp.async ----
    {
        int r = tid & 127;
        const float* src = (tid < 128) ? (xb + (size_t)(i0 + r) * DDIM)
                                       : (yb + (size_t)(j0 + r) * DDIM);
        float s = 0.f;
#pragma unroll
        for (int cc = 0; cc < 16; cc++) {
            float4 v = __ldg((const float4*)(src + cc * 4));
            s += v.x * v.x + v.y * v.y + v.z * v.z + v.w * v.w;
        }
        if (tid < 128) xn_s[r] = s;
        else           yn_s[r] = s;
    }

    asm volatile("cp.async.wait_group 0;");
    __syncthreads();

    float acc[4][4][4];
#pragma unroll
    for (int fm = 0; fm < 4; fm++)
#pragma unroll
        for (int fn = 0; fn < 4; fn++)
#pragma unroll
            for (int cc = 0; cc < 4; cc++) acc[fm][fn][cc] = 0.f;

    // ---- 8 k-steps, no barriers: ptxas pipelines LDS across MMAs.
    //      Operands are raw fp32; HMMA.tf32 truncates to tf32 in HW. ----
#pragma unroll
    for (int ks = 0; ks < 8; ks++) {
        const int kk = ks * 8;
        uint32_t a[4][4], bb[4][2];
#pragma unroll
        for (int fm = 0; fm < 4; fm++) {
            int mb = wr * 64 + fm * 16 + g;
            a[fm][0] = xs[(mb)     * SK + kk + tig];
            a[fm][1] = xs[(mb + 8) * SK + kk + tig];
            a[fm][2] = xs[(mb)     * SK + kk + tig + 4];
            a[fm][3] = xs[(mb + 8) * SK + kk + tig + 4];
        }
#pragma unroll
        for (int fn = 0; fn < 4; fn++) {
            int nb = wc * 32 + fn * 8 + g;
            bb[fn][0] = ys[nb * SK + kk + tig];
            bb[fn][1] = ys[nb * SK + kk + tig + 4];
        }
#pragma unroll
        for (int fm = 0; fm < 4; fm++)
#pragma unroll
            for (int fn = 0; fn < 4; fn++)
                asm volatile(
                    "mma.sync.aligned.m16n8k8.row.col.f32.tf32.tf32.f32 "
                    "{%0,%1,%2,%3}, {%4,%5,%6,%7}, {%8,%9}, {%0,%1,%2,%3};"
                    : "+f"(acc[fm][fn][0]), "+f"(acc[fm][fn][1]),
                      "+f"(acc[fm][fn][2]), "+f"(acc[fm][fn][3])
                    : "r"(a[fm][0]), "r"(a[fm][1]),
                      "r"(a[fm][2]), "r"(a[fm][3]),
                      "r"(bb[fn][0]), "r"(bb[fn][1]));
    }

    // ---- epilogue: out = xnorm + ynorm - 2*dot (norms exact fp32) ----
    float* outb = out + (size_t)b * NROWS * NROWS;

#pragma unroll
    for (int fm = 0; fm < 4; fm++) {
        int rl = wr * 64 + fm * 16 + g;
        int r0 = i0 + rl;
        float xn0 = xn_s[rl];
        float xn1 = xn_s[rl + 8];
#pragma unroll
        for (int fn = 0; fn < 4; fn++) {
            int cl = wc * 32 + fn * 8 + 2 * tig;
            int c = j0 + cl;
            float yn0 = yn_s[cl];
            float yn1 = yn_s[cl + 1];
            float2 v0, v1;
            v0.x = xn0 + yn0 - 2.f * acc[fm][fn][0];
            v0.y = xn0 + yn1 - 2.f * acc[fm][fn][1];
            v1.x = xn1 + yn0 - 2.f * acc[fm][fn][2];
            v1.y = xn1 + yn1 - 2.f * acc[fm][fn][3];
            *(float2*)(outb + (size_t)r0 * NROWS + c)       = v0;
            *(float2*)(outb + (size_t)(r0 + 8) * NROWS + c) = v1;
        }
    }
}

// ---------------------------------------------------------------------------
extern "C" void kernel_launch(void* const* d_in, const int* in_sizes, int n_in,
                              void* d_out, int out_size) {
    const float* x = (const float*)d_in[0];
    const float* y = (const float*)d_in[1];
    float* out = (float*)d_out;

    cudaFuncSetAttribute(pdist_kernel,
                         cudaFuncAttributeMaxDynamicSharedMemorySize,
                         SMEM_TOTAL);

    dim3 grid(NROWS / BN, NROWS / BM, BATCH);   // 16 x 16 x 2
    pdist_kernel<<<grid, 256, SMEM_TOTAL>>>(x, y, out);
}

// round 11
// speedup vs baseline: 1.7262x; 1.7262x over previous
#include <cuda_runtime.h>
#include <cstdint>

// PairwiseDistance: out[b,i,j] = ||x_i||^2 + ||y_j||^2 - 2*<x_i,y_j>
// Cross term via mma.sync tf32, operands fed raw fp32 (HW truncates to tf32).
// Fragments loaded with ldmatrix (6 LDSM + 16 MMA per warp-kstep).
// Norms exact fp32 via in-prologue shuffle reduction.  B=2, n=2048, d=64.

#define BATCH 2
#define NROWS 2048
#define DDIM  64

#define BM 128
#define BN 128
#define SK 68        // smem row stride in floats (64 + 4 pad)

#define SMEM_X  0
#define SMEM_Y  (BM * SK * 4)
#define SMEM_XN (2 * BM * SK * 4)
#define SMEM_YN (SMEM_XN + 512)
#define SMEM_TOTAL (SMEM_YN + 512)         // 70656 B

__device__ __forceinline__ uint32_t smem_u32(const void* p) {
    uint32_t a;
    asm("{ .reg .u64 t; cvta.to.shared.u64 t, %1; cvt.u32.u64 %0, t; }"
        : "=r"(a) : "l"(p));
    return a;
}

__global__ void __launch_bounds__(256, 2)
pdist_kernel(const float* __restrict__ x,
             const float* __restrict__ y,
             float* __restrict__ out) {
    extern __shared__ char smem[];
    uint32_t* xs = (uint32_t*)(smem + SMEM_X);
    uint32_t* ys = (uint32_t*)(smem + SMEM_Y);
    float* xn_s  = (float*)(smem + SMEM_XN);
    float* yn_s  = (float*)(smem + SMEM_YN);

    const int b  = blockIdx.z;
    const int i0 = blockIdx.y * BM;
    const int j0 = blockIdx.x * BN;
    const int tid = threadIdx.x;

    const float* xb = x + (size_t)b * NROWS * DDIM;
    const float* yb = y + (size_t)b * NROWS * DDIM;

    const int warp = tid >> 5;
    const int lane = tid & 31;
    const int wr = warp >> 2;          // 0..1
    const int wc = warp & 3;           // 0..3
    const int g   = lane >> 2;         // 0..7
    const int tig = lane & 3;          // 0..3

    // ---- prologue: LDG float4, norms via 16-lane shuffle, STS.128 raw bits ----
    // thread -> (row r = e>>4, chunk c = e&15); 16 consecutive tids = one row.
#pragma unroll
    for (int i = 0; i < 8; i++) {
        int e = tid + i * 256;
        int r = e >> 4;
        int c = e & 15;
        float4 vx = *(const float4*)(xb + (size_t)(i0 + r) * DDIM + c * 4);
        float4 vy = *(const float4*)(yb + (size_t)(j0 + r) * DDIM + c * 4);

        float sx = vx.x * vx.x + vx.y * vx.y + vx.z * vx.z + vx.w * vx.w;
        float sy = vy.x * vy.x + vy.y * vy.y + vy.z * vy.z + vy.w * vy.w;
#pragma unroll
        for (int m = 1; m < 16; m <<= 1) {
            sx += __shfl_xor_sync(0xFFFFFFFFu, sx, m);
            sy += __shfl_xor_sync(0xFFFFFFFFu, sy, m);
        }
        if (c == 0) { xn_s[r] = sx; yn_s[r] = sy; }

        *(float4*)(xs + r * SK + c * 4) = vx;   // raw fp32 bits
        *(float4*)(ys + r * SK + c * 4) = vy;
    }
    __syncthreads();

    float acc[4][4][4];
#pragma unroll
    for (int fm = 0; fm < 4; fm++)
#pragma unroll
        for (int fn = 0; fn < 4; fn++)
#pragma unroll
            for (int cc = 0; cc < 4; cc++) acc[fm][fn][cc] = 0.f;

    // ---- per-lane ldmatrix base addresses (bytes) ----
    // A x4 (per fm): m0 rows mb+0..7 koff 0 | m1 rows +8..15 koff 0
    //               | m2 rows +0..7 koff 4 | m3 rows +8..15 koff 4
    //   lane l: row = wr*64 + (l&15), koff = (l>>4)*4
    const uint32_t xs_a = smem_u32(xs);
    const uint32_t ys_a = smem_u32(ys);
    uint32_t a_addr = xs_a + (((wr * 64 + (lane & 15)) * SK + (lane >> 4) * 4) << 2);
    // B x4 (per fn-pair p, fn=2p): m0 rows nb+0..7 koff 0 | m1 same rows koff 4
    //               | m2 rows nb+8..15 koff 0 | m3 rows +8..15 koff 4
    //   lane l: row = wc*32 + (l&7) + (l>>4)*8, koff = ((l>>3)&1)*4
    uint32_t b_addr = ys_a + (((wc * 32 + (lane & 7) + (lane >> 4) * 8) * SK +
                               ((lane >> 3) & 1) * 4) << 2);

    // ---- mainloop: 6 LDSM + 16 MMA per kstep, no barriers ----
#pragma unroll
    for (int ks = 0; ks < 8; ks++) {
        uint32_t a[4][4], bb[4][2];
#pragma unroll
        for (int fm = 0; fm < 4; fm++) {
            uint32_t ad = a_addr + fm * (16 * SK * 4) + ks * 32;
            asm volatile(
                "ldmatrix.sync.aligned.m8n8.x4.shared.b16 {%0,%1,%2,%3}, [%4];"
                : "=r"(a[fm][0]), "=r"(a[fm][1]), "=r"(a[fm][2]), "=r"(a[fm][3])
                : "r"(ad));
        }
#pragma unroll
        for (int p = 0; p < 2; p++) {
            uint32_t bd = b_addr + p * (16 * SK * 4) + ks * 32;
            asm volatile(
                "ldmatrix.sync.aligned.m8n8.x4.shared.b16 {%0,%1,%2,%3}, [%4];"
                : "=r"(bb[2 * p][0]), "=r"(bb[2 * p][1]),
                  "=r"(bb[2 * p + 1][0]), "=r"(bb[2 * p + 1][1])
                : "r"(bd));
        }
#pragma unroll
        for (int fm = 0; fm < 4; fm++)
#pragma unroll
            for (int fn = 0; fn < 4; fn++)
                asm volatile(
                    "mma.sync.aligned.m16n8k8.row.col.f32.tf32.tf32.f32 "
                    "{%0,%1,%2,%3}, {%4,%5,%6,%7}, {%8,%9}, {%0,%1,%2,%3};"
                    : "+f"(acc[fm][fn][0]), "+f"(acc[fm][fn][1]),
                      "+f"(acc[fm][fn][2]), "+f"(acc[fm][fn][3])
                    : "r"(a[fm][0]), "r"(a[fm][1]),
                      "r"(a[fm][2]), "r"(a[fm][3]),
                      "r"(bb[fn][0]), "r"(bb[fn][1]));
    }

    // ---- epilogue: out = xnorm + ynorm - 2*dot ----
    float* outb = out + (size_t)b * NROWS * NROWS;

#pragma unroll
    for (int fm = 0; fm < 4; fm++) {
        int rl = wr * 64 + fm * 16 + g;
        int r0 = i0 + rl;
        float xn0 = xn_s[rl];
        float xn1 = xn_s[rl + 8];
#pragma unroll
        for (int fn = 0; fn < 4; fn++) {
            int cl = wc * 32 + fn * 8 + 2 * tig;
            int c = j0 + cl;
            float yn0 = yn_s[cl];
            float yn1 = yn_s[cl + 1];
            float2 v0, v1;
            v0.x = xn0 + yn0 - 2.f * acc[fm][fn][0];
            v0.y = xn0 + yn1 - 2.f * acc[fm][fn][1];
            v1.x = xn1 + yn0 - 2.f * acc[fm][fn][2];
            v1.y = xn1 + yn1 - 2.f * acc[fm][fn][3];
            *(float2*)(outb + (size_t)r0 * NROWS + c)       = v0;
            *(float2*)(outb + (size_t)(r0 + 8) * NROWS + c) = v1;
        }
    }
}

// ---------------------------------------------------------------------------
extern "C" void kernel_launch(void* const* d_in, const int* in_sizes, int n_in,
                              void* d_out, int out_size) {
    const float* x = (const float*)d_in[0];
    const float* y = (const float*)d_in[1];
    float* out = (float*)d_out;

    cudaFuncSetAttribute(pdist_kernel,
                         cudaFuncAttributeMaxDynamicSharedMemorySize,
                         SMEM_TOTAL);

    dim3 grid(NROWS / BN, NROWS / BM, BATCH);   // 16 x 16 x 2
    pdist_kernel<<<grid, 256, SMEM_TOTAL>>>(x, y, out);
}

// round 12
// speedup vs baseline: 1.7525x; 1.0153x over previous
#include <cuda_runtime.h>
#include <cstdint>

// PairwiseDistance: out[b,i,j] = ||x_i||^2 + ||y_j||^2 - 2*<x_i,y_j>
// mma.sync tf32, raw fp32 operands (HW truncation). ldmatrix fragments.
// CTA tile 128x64, warp tile 32x32, 8 warps -> ~80 regs -> 3 CTAs/SM.
// B=2, n=2048, d=64.

#define BATCH 2
#define NROWS 2048
#define DDIM  64

#define BM 128
#define BN 64
#define SK 68        // smem row stride in floats (64 + 4 pad)

#define SMEM_X  0
#define SMEM_Y  (BM * SK * 4)                  // 34816
#define SMEM_XN (SMEM_Y + BN * SK * 4)         // +17408 = 52224
#define SMEM_YN (SMEM_XN + BM * 4)
#define SMEM_TOTAL (SMEM_YN + BN * 4)          // 53248 B

__device__ __forceinline__ uint32_t smem_u32(const void* p) {
    uint32_t a;
    asm("{ .reg .u64 t; cvta.to.shared.u64 t, %1; cvt.u32.u64 %0, t; }"
        : "=r"(a) : "l"(p));
    return a;
}

__global__ void __launch_bounds__(256, 3)
pdist_kernel(const float* __restrict__ x,
             const float* __restrict__ y,
             float* __restrict__ out) {
    extern __shared__ char smem[];
    uint32_t* xs = (uint32_t*)(smem + SMEM_X);
    uint32_t* ys = (uint32_t*)(smem + SMEM_Y);
    float* xn_s  = (float*)(smem + SMEM_XN);
    float* yn_s  = (float*)(smem + SMEM_YN);

    const int b  = blockIdx.z;
    const int i0 = blockIdx.y * BM;
    const int j0 = blockIdx.x * BN;
    const int tid = threadIdx.x;

    const float* xb = x + (size_t)b * NROWS * DDIM;
    const float* yb = y + (size_t)b * NROWS * DDIM;

    const int warp = tid >> 5;
    const int lane = tid & 31;
    const int wr = warp >> 1;          // 0..3  (32 rows each)
    const int wc = warp & 1;           // 0..1  (32 cols each)
    const int g   = lane >> 2;         // 0..7
    const int tig = lane & 3;          // 0..3

    // ---- prologue: LDG float4, exact-fp32 norms via 16-lane shuffle, STS ----
    // thread -> (row r = e>>4, chunk c = e&15); 16 consecutive tids = one row.
#pragma unroll
    for (int i = 0; i < 8; i++) {
        int e = tid + i * 256;
        int r = e >> 4;
        int c = e & 15;
        float4 vx = *(const float4*)(xb + (size_t)(i0 + r) * DDIM + c * 4);
        float sx = vx.x * vx.x + vx.y * vx.y + vx.z * vx.z + vx.w * vx.w;
#pragma unroll
        for (int m = 1; m < 16; m <<= 1)
            sx += __shfl_xor_sync(0xFFFFFFFFu, sx, m);
        if (c == 0) xn_s[r] = sx;
        *(float4*)(xs + r * SK + c * 4) = vx;
    }
#pragma unroll
    for (int i = 0; i < 4; i++) {
        int e = tid + i * 256;
        int r = e >> 4;                // 0..63
        int c = e & 15;
        float4 vy = *(const float4*)(yb + (size_t)(j0 + r) * DDIM + c * 4);
        float sy = vy.x * vy.x + vy.y * vy.y + vy.z * vy.z + vy.w * vy.w;
#pragma unroll
        for (int m = 1; m < 16; m <<= 1)
            sy += __shfl_xor_sync(0xFFFFFFFFu, sy, m);
        if (c == 0) yn_s[r] = sy;
        *(float4*)(ys + r * SK + c * 4) = vy;
    }
    __syncthreads();

    float acc[2][4][4];
#pragma unroll
    for (int fm = 0; fm < 2; fm++)
#pragma unroll
        for (int fn = 0; fn < 4; fn++)
#pragma unroll
            for (int cc = 0; cc < 4; cc++) acc[fm][fn][cc] = 0.f;

    // ---- ldmatrix base addresses (verified mapping, rebased) ----
    // A x4 per fm: lane l -> row wr*32 + fm*16 + (l&15), koff (l>>4)*4
    // B x4 per p (fn=2p,2p+1): lane l -> row wc*32 + p*16 + (l&7)+(l>>4)*8,
    //                          koff ((l>>3)&1)*4
    const uint32_t xs_a = smem_u32(xs);
    const uint32_t ys_a = smem_u32(ys);
    uint32_t a_addr = xs_a + (((wr * 32 + (lane & 15)) * SK + (lane >> 4) * 4) << 2);
    uint32_t b_addr = ys_a + (((wc * 32 + (lane & 7) + (lane >> 4) * 8) * SK +
                               ((lane >> 3) & 1) * 4) << 2);

    // ---- mainloop: 4 LDSM + 8 MMA per kstep, no barriers ----
#pragma unroll
    for (int ks = 0; ks < 8; ks++) {
        uint32_t a[2][4], bb[4][2];
#pragma unroll
        for (int fm = 0; fm < 2; fm++) {
            uint32_t ad = a_addr + fm * (16 * SK * 4) + ks * 32;
            asm volatile(
                "ldmatrix.sync.aligned.m8n8.x4.shared.b16 {%0,%1,%2,%3}, [%4];"
                : "=r"(a[fm][0]), "=r"(a[fm][1]), "=r"(a[fm][2]), "=r"(a[fm][3])
                : "r"(ad));
        }
#pragma unroll
        for (int p = 0; p < 2; p++) {
            uint32_t bd = b_addr + p * (16 * SK * 4) + ks * 32;
            asm volatile(
                "ldmatrix.sync.aligned.m8n8.x4.shared.b16 {%0,%1,%2,%3}, [%4];"
                : "=r"(bb[2 * p][0]), "=r"(bb[2 * p][1]),
                  "=r"(bb[2 * p + 1][0]), "=r"(bb[2 * p + 1][1])
                : "r"(bd));
        }
#pragma unroll
        for (int fm = 0; fm < 2; fm++)
#pragma unroll
            for (int fn = 0; fn < 4; fn++)
                asm volatile(
                    "mma.sync.aligned.m16n8k8.row.col.f32.tf32.tf32.f32 "
                    "{%0,%1,%2,%3}, {%4,%5,%6,%7}, {%8,%9}, {%0,%1,%2,%3};"
                    : "+f"(acc[fm][fn][0]), "+f"(acc[fm][fn][1]),
                      "+f"(acc[fm][fn][2]), "+f"(acc[fm][fn][3])
                    : "r"(a[fm][0]), "r"(a[fm][1]),
                      "r"(a[fm][2]), "r"(a[fm][3]),
                      "r"(bb[fn][0]), "r"(bb[fn][1]));
    }

    // ---- epilogue: out = xnorm + ynorm - 2*dot ----
    float* outb = out + (size_t)b * NROWS * NROWS;

#pragma unroll
    for (int fm = 0; fm < 2; fm++) {
        int rl = wr * 32 + fm * 16 + g;
        int r0 = i0 + rl;
        float xn0 = xn_s[rl];
        float xn1 = xn_s[rl + 8];
#pragma unroll
        for (int fn = 0; fn < 4; fn++) {
            int cl = wc * 32 + fn * 8 + 2 * tig;
            int c = j0 + cl;
            float yn0 = yn_s[cl];
            float yn1 = yn_s[cl + 1];
            float2 v0, v1;
            v0.x = xn0 + yn0 - 2.f * acc[fm][fn][0];
            v0.y = xn0 + yn1 - 2.f * acc[fm][fn][1];
            v1.x = xn1 + yn0 - 2.f * acc[fm][fn][2];
            v1.y = xn1 + yn1 - 2.f * acc[fm][fn][3];
            *(float2*)(outb + (size_t)r0 * NROWS + c)       = v0;
            *(float2*)(outb + (size_t)(r0 + 8) * NROWS + c) = v1;
        }
    }
}

// ---------------------------------------------------------------------------
extern "C" void kernel_launch(void* const* d_in, const int* in_sizes, int n_in,
                              void* d_out, int out_size) {
    const float* x = (const float*)d_in[0];
    const float* y = (const float*)d_in[1];
    float* out = (float*)d_out;

    cudaFuncSetAttribute(pdist_kernel,
                         cudaFuncAttributeMaxDynamicSharedMemorySize,
                         SMEM_TOTAL);

    dim3 grid(NROWS / BN, NROWS / BM, BATCH);   // 32 x 16 x 2
    pdist_kernel<<<grid, 256, SMEM_TOTAL>>>(x, y, out);
}